// round 11
// baseline (speedup 1.0000x reference)
#include <cuda_runtime.h>

// ---------------------------------------------------------------------------
// GlimpseNetwork fused pipeline.  B=4096, H=128, G=14, patches 14/28/56/112.
// Fragment-major tf32 MMA GEMMs; gemm2 single-phase (full K resident).
// ---------------------------------------------------------------------------

#define BATCH 4096
#define HIMG  128
#define PHI_DIM 784

// Scratch (device globals; no cudaMalloc allowed)
__device__ __align__(16) float g_phif[PHI_DIM * BATCH];    // tf32 frag-major (A of gemm1)
__device__ __align__(16) float g_h1wf[BATCH * 128];        // f32 frag-major (A of gemm2 what)
__device__ __align__(16) float g_h1lf[BATCH * 128];        // f32 frag-major (A of gemm2 where)
__device__ __align__(16) float g_W1f[PHI_DIM * 128];       // tf32 frag-major B
__device__ __align__(16) float g_W2wf[128 * 256];
__device__ __align__(16) float g_W2lf[128 * 256];
__device__ __align__(16) float g_h2w[BATCH * 256];
__device__ __align__(16) float g_h2l[BATCH * 256];
// per-block column partials (deterministic: no atomics)
__device__ float g_p1w_s[64 * 128],  g_p1w_q[64 * 128];
__device__ float g_p1l_s[32 * 128],  g_p1l_q[32 * 128];
__device__ float g_p2w_s[64 * 256],  g_p2w_q[64 * 256];
__device__ float g_p2l_s[64 * 256],  g_p2l_q[64 * 256];
// fused BN transforms: h_norm = fma(h, scale, shift)
__device__ float g_s1w[128], g_t1w[128], g_s1l[128], g_t1l[128];
__device__ float g_s2w[256], g_t2w[256], g_s2l[256], g_t2l[256];

__device__ __forceinline__ unsigned f2tf(float v) {
    unsigned r;
    asm("cvt.rna.tf32.f32 %0, %1;" : "=r"(r) : "f"(v));
    return r;
}

__device__ __forceinline__ void mma_tf32(float* d, const unsigned* a, const unsigned* b) {
    asm volatile(
        "mma.sync.aligned.m16n8k8.row.col.f32.tf32.tf32.f32 "
        "{%0,%1,%2,%3}, {%4,%5,%6,%7}, {%8,%9}, {%0,%1,%2,%3};"
        : "+f"(d[0]), "+f"(d[1]), "+f"(d[2]), "+f"(d[3])
        : "r"(a[0]), "r"(a[1]), "r"(a[2]), "r"(a[3]), "r"(b[0]), "r"(b[1]));
}

// B (weights, K x N row-major input) -> tf32 fragment-major.
__device__ __forceinline__ void conv_frag(const float* __restrict__ W,
                                          float* __restrict__ Wf,
                                          int Kw, int Nw, int tid0, int nthreads)
{
    int total = Kw * Nw;
    for (int e = tid0; e < total; e += nthreads) {
        int kk = e / Nw, n = e - kk * Nw;
        int pos = (kk >> 4) * (Nw * 16)
                + (((kk >> 3) & 1) * (Nw >> 4) + (n >> 4)) * 128
                + (((n & 7) << 2) + (kk & 3)) * 4
                + (((n >> 3) & 1) << 1) + ((kk >> 2) & 1);
        Wf[pos] = __uint_as_float(f2tf(W[e]));
    }
}

// A fragment-major word index for element (m, k), M rows total.
__device__ __forceinline__ size_t posA(int m, int k, int M)
{
    return (size_t)(k >> 4) * (M * 16)
         + (size_t)(((k >> 3) & 1) * (M >> 4) + (m >> 4)) * 128
         + (((m & 7) << 2) + (k & 3)) * 4
         + ((m >> 3) & 1) + (((k >> 2) & 1) << 1);
}

// ---------------------------------------------------------------------------
// 1) Foveate: one sample per block (4096 blocks, 256 threads), 2x2-pooled
//    pyramid in SMEM, phi written tf32 fragment-major (scatter).
//    Aux: 0..31 where-layer1 (frag out), 32..79 W1 conv, 80..87 W2w, 88..95 W2l.
// ---------------------------------------------------------------------------
__global__ void __launch_bounds__(256) foveate_kernel(
    const float* __restrict__ x,
    const float* __restrict__ loc,
    const float* __restrict__ lW1,
    const float* __restrict__ lb1,
    const float* __restrict__ wW1,
    const float* __restrict__ wW2,
    const float* __restrict__ lW2)
{
    __shared__ float pooled[56 * 57];
    __shared__ float center[196];
    __shared__ float wrs[256], wrq[256];
    int tid = threadIdx.x;
    int b = blockIdx.x;

    float lx = loc[2 * b + 0];
    float ly = loc[2 * b + 1];
    int cx = (int)(0.5f * ((lx + 1.0f) * 128.0f));
    int cy = (int)(0.5f * ((ly + 1.0f) * 128.0f));
    int row0 = cy - 56;
    int col0 = cx - 56;
    const float* __restrict__ img = x + (size_t)b * HIMG * HIMG;

    for (int idx = tid; idx < 56 * 56; idx += 256) {
        int pr = idx / 56;
        int pc = idx - pr * 56;
        int r = row0 + 2 * pr;
        int c = col0 + 2 * pc;
        float sm = 0.0f;
        bool r0ok = (unsigned)r < 128u, r1ok = (unsigned)(r + 1) < 128u;
        bool c0ok = (unsigned)c < 128u, c1ok = (unsigned)(c + 1) < 128u;
        if (r0ok && c0ok) sm += img[r * HIMG + c];
        if (r0ok && c1ok) sm += img[r * HIMG + c + 1];
        if (r1ok && c0ok) sm += img[(r + 1) * HIMG + c];
        if (r1ok && c1ok) sm += img[(r + 1) * HIMG + c + 1];
        pooled[pr * 57 + pc] = sm * 0.25f;
    }
    if (tid < 196) {
        int i = tid / 14;
        int j = tid - i * 14;
        int r = row0 + 49 + i;
        int c = col0 + 49 + j;
        float v = 0.0f;
        if ((unsigned)r < 128u && (unsigned)c < 128u) v = img[r * HIMG + c];
        center[tid] = v;
    }
    __syncthreads();

    for (int o = tid; o < PHI_DIM; o += 256) {
        int p = o / 196;
        int rem = o - p * 196;
        int i = rem / 14;
        int j = rem - i * 14;
        float v;
        if (p == 0) {
            v = center[rem];
        } else if (p == 1) {
            v = pooled[(21 + i) * 57 + 21 + j];
        } else if (p == 2) {
            int base = (14 + 2 * i) * 57 + 14 + 2 * j;
            v = (pooled[base] + pooled[base + 1] +
                 pooled[base + 57] + pooled[base + 58]) * 0.25f;
        } else {
            int base = (4 * i) * 57 + 4 * j;
            float sm = 0.0f;
            #pragma unroll
            for (int di = 0; di < 4; di++)
                #pragma unroll
                for (int dj = 0; dj < 4; dj++)
                    sm += pooled[base + di * 57 + dj];
            v = sm * (1.0f / 16.0f);
        }
        g_phif[posA(b, o, BATCH)] = __uint_as_float(f2tf(v));
    }

    // ---- folded aux work ----
    if (b < 32) {
        int c = tid & 127;
        int half = tid >> 7;
        int r0 = b * 128 + half * 64;
        float w0 = lW1[c], w1 = lW1[128 + c], bb = lb1[c];
        float s = 0.0f, q = 0.0f;
        for (int r = r0; r < r0 + 64; r++) {
            float2 l = ((const float2*)loc)[r];
            float v = fmaf(l.x, w0, fmaf(l.y, w1, bb));
            g_h1lf[posA(r, c, BATCH)] = v;
            s += v;
            q += v * v;
        }
        wrs[tid] = s;
        wrq[tid] = q;
        __syncthreads();
        if (tid < 128) {
            g_p1l_s[b * 128 + tid] = wrs[tid] + wrs[tid + 128];
            g_p1l_q[b * 128 + tid] = wrq[tid] + wrq[tid + 128];
        }
    } else if (b < 80) {
        conv_frag(wW1, g_W1f, PHI_DIM, 128, (b - 32) * 256 + tid, 48 * 256);
    } else if (b < 88) {
        conv_frag(wW2, g_W2wf, 128, 256, (b - 80) * 256 + tid, 8 * 256);
    } else if (b < 96) {
        conv_frag(lW2, g_W2lf, 128, 256, (b - 88) * 256 + tid, 8 * 256);
    }
}

// ---------------------------------------------------------------------------
// 2) gemm1: BM=64 BN=64, grid (2,64)=128 blocks. 8 warps = 2m x 4n, warp tile
//    32x16. 2-stage pipeline over K=784. Emits h1w frag + stats partials.
// ---------------------------------------------------------------------------
__global__ void __launch_bounds__(256) gemm1_kernel(const float* __restrict__ b1)
{
    constexpr int BM = 64, BN = 64;
    constexpr int STAGE_A = BM * 16;   // 1024 floats
    constexpr int STAGE_B = BN * 16;   // 1024 floats
    constexpr int STAGE = STAGE_A + STAGE_B;   // 2048
    constexpr int CSS = BN + 4;        // 68
    constexpr int BUFSZ = (2 * STAGE > BM * CSS) ? 2 * STAGE : BM * CSS;  // 4352
    constexpr int STEPS = PHI_DIM / 16;  // 49

    __shared__ __align__(16) float buf[BUFSZ];
    __shared__ float rs[256], rq[256];

    const uint4*  Af = (const uint4*)g_phif;
    const float4* Bf = (const float4*)g_W1f;

    int tid = threadIdx.x;
    int lane = tid & 31;
    int wid = tid >> 5;
    int wn = wid & 3;    // 0..3
    int wm = wid >> 2;   // 0..1
    int nb = blockIdx.x; // 0..1
    int m0 = blockIdx.y * BM;
    int n0 = nb * BN;

    uint4  aReg;
    float4 bReg;

    auto ldA = [&](int step) {
        int f = tid >> 5;
        int k8 = f >> 2, mt = f & 3;
        aReg = Af[(size_t)step * 16384 + (size_t)(k8 * 256 + (m0 >> 4) + mt) * 32 + lane];
    };
    auto ldB = [&](int step) {
        // per step: 2 k8 x 4 n16-chunks x 32 lanes = 256 float4
        int k8 = tid >> 7;
        int nc = (tid >> 5) & 3;
        bReg = Bf[(size_t)step * 512 + (size_t)(k8 * 8 + (n0 >> 4) + nc) * 32 + lane];
    };
    auto stA = [&](float* As) { ((uint4*)As)[tid] = aReg; };
    auto stB = [&](float* Bs) { ((float4*)Bs)[tid] = bReg; };

    float acc[2][2][4];
    #pragma unroll
    for (int i = 0; i < 2; i++)
        #pragma unroll
        for (int j = 0; j < 2; j++)
            #pragma unroll
            for (int v = 0; v < 4; v++) acc[i][j][v] = 0.0f;

    auto compute = [&](const float* As, const float* Bs) {
        #pragma unroll
        for (int k8 = 0; k8 < 2; k8++) {
            unsigned a[2][4];
            #pragma unroll
            for (int i = 0; i < 2; i++)
                *(uint4*)a[i] = *(const uint4*)&((const unsigned*)As)[
                    (k8 * 4 + wm * 2 + i) * 128 + lane * 4];
            uint4 bb = *(const uint4*)&((const unsigned*)Bs)[
                (k8 * 4 + wn) * 128 + lane * 4];
            unsigned bl[2] = {bb.x, bb.y};
            unsigned bh[2] = {bb.z, bb.w};
            #pragma unroll
            for (int i = 0; i < 2; i++) {
                mma_tf32(acc[i][0], a[i], bl);
                mma_tf32(acc[i][1], a[i], bh);
            }
        }
    };

    ldA(0); ldB(0);
    stA(buf); stB(buf + STAGE_A);
    ldA(1); ldB(1);
    __syncthreads();

    for (int s = 0; s < STEPS; s++) {
        int cur = s & 1, nxt = cur ^ 1;
        float* curBuf = buf + cur * STAGE;
        if (s + 1 < STEPS) {
            float* nxtBuf = buf + nxt * STAGE;
            stA(nxtBuf);
            stB(nxtBuf + STAGE_A);
        }
        if (s + 2 < STEPS) { ldA(s + 2); ldB(s + 2); }
        compute(curBuf, curBuf + STAGE_A);
        __syncthreads();
    }

    // fragments -> Cs (stride 68)
    float* Cs = buf;
    #pragma unroll
    for (int i = 0; i < 2; i++) {
        int row = (wm * 2 + i) * 16 + (lane >> 2);
        #pragma unroll
        for (int j = 0; j < 2; j++) {
            int cb = wn * 16 + j * 8 + 2 * (lane & 3);
            *(float2*)&Cs[row * CSS + cb]       = make_float2(acc[i][j][0], acc[i][j][1]);
            *(float2*)&Cs[(row + 8) * CSS + cb] = make_float2(acc[i][j][2], acc[i][j][3]);
        }
    }
    __syncthreads();

    // bias + stats, store back to Cs
    {
        int c = tid & 63;
        int h = tid >> 6;            // 0..3, 16 rows each
        float bb = b1[n0 + c];
        float s = 0.0f, q = 0.0f;
        #pragma unroll
        for (int i = 0; i < 16; i++) {
            int r = h * 16 + i;
            float v = Cs[r * CSS + c] + bb;
            Cs[r * CSS + c] = v;
            s += v;
            q += v * v;
        }
        rs[tid] = s;
        rq[tid] = q;
    }
    __syncthreads();
    if (tid < 64) {
        g_p1w_s[blockIdx.y * 128 + n0 + tid] = rs[tid] + rs[tid + 64] + rs[tid + 128] + rs[tid + 192];
        g_p1w_q[blockIdx.y * 128 + n0 + tid] = rq[tid] + rq[tid + 64] + rq[tid + 128] + rq[tid + 192];
    }
    __syncthreads();

    // emit raw-f32 fragment-major h1w: 64x64 tile -> 1024 float4, 4/thread
    #pragma unroll
    for (int i2 = 0; i2 < 4; i2++) {
        int u = tid + i2 * 256;
        int l = u & 31;
        int f = u >> 5;           // 0..31
        int cl = f >> 3;          // local n16 chunk 0..3
        int rf = f & 7;
        int k8 = rf >> 2;
        int mt = rf & 3;
        int nl = cl * 16 + k8 * 8 + (l & 3);
        int rl = mt * 16 + (l >> 2);
        float4 o = make_float4(Cs[rl * CSS + nl],     Cs[(rl + 8) * CSS + nl],
                               Cs[rl * CSS + nl + 4], Cs[(rl + 8) * CSS + nl + 4]);
        ((float4*)g_h1wf)[(size_t)((n0 >> 4) + cl) * 16384 +
                          (size_t)(k8 * 256 + (m0 >> 4) + mt) * 32 + l] = o;
    }
}

// ---------------------------------------------------------------------------
// 3) gemm2: single-phase full-K-resident tf32 MMA. BM=64 BN=64 K=128.
//    64KB dyn SMEM (A 32K + B 32K), grid (4,64,2) = 512 blocks, 3 blocks/SM.
//    8 warps = 2m x 4n, warp tile 32x16.
// ---------------------------------------------------------------------------
#define G2_SMEM (16384 * 4)

__global__ void __launch_bounds__(256) gemm2_kernel(const float* __restrict__ wb2,
                                                    const float* __restrict__ lb2)
{
    extern __shared__ __align__(16) float dbuf[];   // [0,8192) A, [8192,16384) B
    __shared__ float rs[256], rq[256], sSc[128], sSh[128];

    int tid = threadIdx.x;
    int lane = tid & 31;
    int wid = tid >> 5;
    int wn = wid & 3;
    int wm = wid >> 2;
    int nb = blockIdx.x, mb = blockIdx.y, z = blockIdx.z;
    int m0 = mb * 64, n0 = nb * 64;

    const uint4*  Af = (const uint4*)(z ? g_h1lf : g_h1wf);
    const float4* Bf = (const float4*)(z ? g_W2lf : g_W2wf);
    const float*  bias = z ? lb2 : wb2;
    const float*  sA = z ? g_s1l : g_s1w;
    const float*  tA = z ? g_t1l : g_t1w;
    float* Cout = z ? g_h2l : g_h2w;
    float* ps = z ? g_p2l_s : g_p2w_s;
    float* pq = z ? g_p2l_q : g_p2w_q;

    if (tid < 128) { sSc[tid] = sA[tid]; sSh[tid] = tA[tid]; }

    // B panel copy: 8 s-chunks x 256 float4 -> 8 per thread
    float4* Bs = (float4*)(dbuf + 8192);
    {
        int k8 = tid >> 7;
        int nc = (tid >> 5) & 3;
        #pragma unroll
        for (int s = 0; s < 8; s++)
            Bs[s * 256 + tid] =
                Bf[(size_t)s * 1024 + (size_t)(k8 * 16 + (n0 >> 4) + nc) * 32 + lane];
    }
    __syncthreads();   // sSc/sSh visible

    // A panel: LDG.128 frag -> BN+ReLU+cvt -> STS.128
    uint4* As = (uint4*)dbuf;
    {
        int f = tid >> 5;
        int k8 = f >> 2, mt = f & 3;
        int klo = k8 * 8 + (lane & 3);
        #pragma unroll
        for (int s = 0; s < 8; s++) {
            uint4 a = Af[(size_t)s * 16384 + (size_t)(k8 * 256 + (m0 >> 4) + mt) * 32 + lane];
            int kk = s * 16 + klo;
            float sc0 = sSc[kk],     sh0 = sSh[kk];
            float sc4 = sSc[kk + 4], sh4 = sSh[kk + 4];
            uint4 o;
            o.x = f2tf(fmaxf(fmaf(__uint_as_float(a.x), sc0, sh0), 0.0f));
            o.y = f2tf(fmaxf(fmaf(__uint_as_float(a.y), sc0, sh0), 0.0f));
            o.z = f2tf(fmaxf(fmaf(__uint_as_float(a.z), sc4, sh4), 0.0f));
            o.w = f2tf(fmaxf(fmaf(__uint_as_float(a.w), sc4, sh4), 0.0f));
            As[s * 256 + tid] = o;
        }
    }
    __syncthreads();

    // compute: 16 syncless k8 iterations
    float acc[2][2][4];
    #pragma unroll
    for (int i = 0; i < 2; i++)
        #pragma unroll
        for (int j = 0; j < 2; j++)
            #pragma unroll
            for (int v = 0; v < 4; v++) acc[i][j][v] = 0.0f;

    const uint4* Bu = (const uint4*)Bs;
    #pragma unroll
    for (int s = 0; s < 8; s++) {
        #pragma unroll
        for (int k8 = 0; k8 < 2; k8++) {
            uint4 av[2];
            av[0] = As[s * 256 + (k8 * 4 + wm * 2 + 0) * 32 + lane];
            av[1] = As[s * 256 + (k8 * 4 + wm * 2 + 1) * 32 + lane];
            uint4 bb = Bu[s * 256 + (k8 * 4 + wn) * 32 + lane];
            unsigned bl[2] = {bb.x, bb.y};
            unsigned bh[2] = {bb.z, bb.w};
            #pragma unroll
            for (int i = 0; i < 2; i++) {
                mma_tf32(acc[i][0], (unsigned*)&av[i], bl);
                mma_tf32(acc[i][1], (unsigned*)&av[i], bh);
            }
        }
    }
    __syncthreads();   // before Cs overlay

    // fragments -> Cs (overlay dbuf; stride 68)
    float* Cs = dbuf;
    #pragma unroll
    for (int i = 0; i < 2; i++) {
        int row = (wm * 2 + i) * 16 + (lane >> 2);
        #pragma unroll
        for (int j = 0; j < 2; j++) {
            int cb = wn * 16 + j * 8 + 2 * (lane & 3);
            *(float2*)&Cs[row * 68 + cb]       = make_float2(acc[i][j][0], acc[i][j][1]);
            *(float2*)&Cs[(row + 8) * 68 + cb] = make_float2(acc[i][j][2], acc[i][j][3]);
        }
    }
    __syncthreads();

    // bias + row-major store + column stats
    {
        int c = tid & 63;
        int h = tid >> 6;    // 0..3, 16 rows each
        float bb = bias[n0 + c];
        float s = 0.0f, q = 0.0f;
        #pragma unroll
        for (int i = 0; i < 16; i++) {
            int r = h * 16 + i;
            float v = Cs[r * 68 + c] + bb;
            Cout[(size_t)(m0 + r) * 256 + n0 + c] = v;
            s += v;
            q += v * v;
        }
        rs[tid] = s;
        rq[tid] = q;
    }
    __syncthreads();
    if (tid < 64) {
        ps[mb * 256 + n0 + tid] = rs[tid] + rs[tid + 64] + rs[tid + 128] + rs[tid + 192];
        pq[mb * 256 + n0 + tid] = rq[tid] + rq[tid + 64] + rq[tid + 128] + rq[tid + 192];
    }
}

// ---------------------------------------------------------------------------
// 4) Parallel finalize: one block per column.
// ---------------------------------------------------------------------------
__device__ __forceinline__ void reduce_finalize(float s, float q, int c,
                                                const float* __restrict__ gam,
                                                const float* __restrict__ bet,
                                                float* __restrict__ sc_out,
                                                float* __restrict__ sh_out)
{
    __shared__ float rs[128], rq[128];
    rs[threadIdx.x] = s;
    rq[threadIdx.x] = q;
    __syncthreads();
    #pragma unroll
    for (int off = 64; off >= 32; off >>= 1) {
        if (threadIdx.x < off) {
            rs[threadIdx.x] += rs[threadIdx.x + off];
            rq[threadIdx.x] += rq[threadIdx.x + off];
        }
        __syncthreads();
    }
    if (threadIdx.x < 32) {
        float ss = rs[threadIdx.x];
        float qq = rq[threadIdx.x];
        #pragma unroll
        for (int off = 16; off > 0; off >>= 1) {
            ss += __shfl_down_sync(0xffffffffu, ss, off);
            qq += __shfl_down_sync(0xffffffffu, qq, off);
        }
        if (threadIdx.x == 0) {
            float m = ss * (1.0f / BATCH);
            float var = qq * (1.0f / BATCH) - m * m;
            float r = rsqrtf(var + 1e-5f);
            float sc = r * gam[c];
            sc_out[c] = sc;
            sh_out[c] = bet[c] - m * sc;
        }
    }
}

__global__ void finalize1_kernel(const float* __restrict__ g1w, const float* __restrict__ be1w,
                                 const float* __restrict__ g1l, const float* __restrict__ be1l)
{
    int t = threadIdx.x;
    if (blockIdx.x < 128) {
        int c = blockIdx.x;
        float s = (t < 64) ? g_p1w_s[t * 128 + c] : 0.0f;
        float q = (t < 64) ? g_p1w_q[t * 128 + c] : 0.0f;
        reduce_finalize(s, q, c, g1w, be1w, g_s1w, g_t1w);
    } else {
        int c = blockIdx.x - 128;
        float s = (t < 32) ? g_p1l_s[t * 128 + c] : 0.0f;
        float q = (t < 32) ? g_p1l_q[t * 128 + c] : 0.0f;
        reduce_finalize(s, q, c, g1l, be1l, g_s1l, g_t1l);
    }
}

__global__ void finalize2_kernel(const float* __restrict__ g2w, const float* __restrict__ be2w,
                                 const float* __restrict__ g2l, const float* __restrict__ be2l)
{
    int t = threadIdx.x;
    if (blockIdx.x < 256) {
        int c = blockIdx.x;
        float s = (t < 64) ? g_p2w_s[t * 256 + c] : 0.0f;
        float q = (t < 64) ? g_p2w_q[t * 256 + c] : 0.0f;
        reduce_finalize(s, q, c, g2w, be2w, g_s2w, g_t2w);
    } else {
        int c = blockIdx.x - 256;
        float s = (t < 64) ? g_p2l_s[t * 256 + c] : 0.0f;
        float q = (t < 64) ? g_p2l_q[t * 256 + c] : 0.0f;
        reduce_finalize(s, q, c, g2l, be2l, g_s2l, g_t2l);
    }
}

// ---------------------------------------------------------------------------
// 5) Final: out = relu( BN(h2w) + BN(h2l) ), float4 vectorized.
// ---------------------------------------------------------------------------
__global__ void final_kernel(float* __restrict__ out)
{
    int idx = blockIdx.x * 256 + threadIdx.x;   // float4 index
    int c0 = (idx & 63) << 2;
    float4 w = ((const float4*)g_h2w)[idx];
    float4 l = ((const float4*)g_h2l)[idx];
    float4 o;
    o.x = fmaf(w.x, g_s2w[c0+0], g_t2w[c0+0]) + fmaf(l.x, g_s2l[c0+0], g_t2l[c0+0]);
    o.y = fmaf(w.y, g_s2w[c0+1], g_t2w[c0+1]) + fmaf(l.y, g_s2l[c0+1], g_t2l[c0+1]);
    o.z = fmaf(w.z, g_s2w[c0+2], g_t2w[c0+2]) + fmaf(l.z, g_s2l[c0+2], g_t2l[c0+2]);
    o.w = fmaf(w.w, g_s2w[c0+3], g_t2w[c0+3]) + fmaf(l.w, g_s2l[c0+3], g_t2l[c0+3]);
    o.x = o.x > 0.0f ? o.x : 0.0f;
    o.y = o.y > 0.0f ? o.y : 0.0f;
    o.z = o.z > 0.0f ? o.z : 0.0f;
    o.w = o.w > 0.0f ? o.w : 0.0f;
    ((float4*)out)[idx] = o;
}

// ---------------------------------------------------------------------------
extern "C" void kernel_launch(void* const* d_in, const int* in_sizes, int n_in,
                              void* d_out, int out_size)
{
    const float* x    = (const float*)d_in[0];
    const float* loc  = (const float*)d_in[1];
    const float* wW1  = (const float*)d_in[2];
    const float* wb1  = (const float*)d_in[3];
    const float* wg1  = (const float*)d_in[4];
    const float* wbe1 = (const float*)d_in[5];
    const float* wW2  = (const float*)d_in[6];
    const float* wb2  = (const float*)d_in[7];
    const float* wg2  = (const float*)d_in[8];
    const float* wbe2 = (const float*)d_in[9];
    const float* lW1  = (const float*)d_in[10];
    const float* lb1  = (const float*)d_in[11];
    const float* lg1  = (const float*)d_in[12];
    const float* lbe1 = (const float*)d_in[13];
    const float* lW2  = (const float*)d_in[14];
    const float* lb2  = (const float*)d_in[15];
    const float* lg2  = (const float*)d_in[16];
    const float* lbe2 = (const float*)d_in[17];
    float* out = (float*)d_out;

    static int smem_set = 0;
    if (!smem_set) {
        cudaFuncSetAttribute(gemm2_kernel,
                             cudaFuncAttributeMaxDynamicSharedMemorySize, G2_SMEM);
        smem_set = 1;
    }

    // 1) foveate (one sample/block) + where1 + weight conversions
    foveate_kernel<<<BATCH, 256>>>(x, loc, lW1, lb1, wW1, wW2, lW2);

    // 2) what layer1 -> h1w frag (+ stats partials), 128 blocks
    {
        dim3 grid(2, BATCH / 64);
        gemm1_kernel<<<grid, 256>>>(wb1);
    }

    // 3) finalize layer-1 BN params
    finalize1_kernel<<<256, 128>>>(wg1, wbe1, lg1, lbe1);

    // 4) both layer-2 GEMMs, single-phase full-K, 512 blocks
    {
        dim3 grid(4, BATCH / 64, 2);
        gemm2_kernel<<<grid, 256, G2_SMEM>>>(wb2, lb2);
    }

    // 5) finalize layer-2 BN params
    finalize2_kernel<<<512, 128>>>(wg2, wbe2, lg2, lbe2);

    // 6) final add + relu (float4)
    final_kernel<<<BATCH * 64 / 256, 256>>>(out);
}

// round 12
// speedup vs baseline: 1.0569x; 1.0569x over previous
#include <cuda_runtime.h>

// ---------------------------------------------------------------------------
// GlimpseNetwork fused pipeline.  B=4096, H=128, G=14, patches 14/28/56/112.
// Fragment-major tf32 MMA GEMMs; gemm2 single-phase (full K resident, 16 warps).
// ---------------------------------------------------------------------------

#define BATCH 4096
#define HIMG  128
#define PHI_DIM 784

// Scratch (device globals; no cudaMalloc allowed)
__device__ __align__(16) float g_phif[PHI_DIM * BATCH];    // tf32 frag-major (A of gemm1)
__device__ __align__(16) float g_h1wf[BATCH * 128];        // f32 frag-major (A of gemm2 what)
__device__ __align__(16) float g_h1lf[BATCH * 128];        // f32 frag-major (A of gemm2 where)
__device__ __align__(16) float g_W1f[PHI_DIM * 128];       // tf32 frag-major B
__device__ __align__(16) float g_W2wf[128 * 256];
__device__ __align__(16) float g_W2lf[128 * 256];
__device__ __align__(16) float g_h2w[BATCH * 256];
__device__ __align__(16) float g_h2l[BATCH * 256];
// per-block column partials (deterministic: no atomics)
__device__ float g_p1w_s[128 * 128], g_p1w_q[128 * 128];
__device__ float g_p1l_s[32 * 128],  g_p1l_q[32 * 128];
__device__ float g_p2w_s[64 * 256],  g_p2w_q[64 * 256];
__device__ float g_p2l_s[64 * 256],  g_p2l_q[64 * 256];
// fused BN transforms: h_norm = fma(h, scale, shift)
__device__ float g_s1w[128], g_t1w[128], g_s1l[128], g_t1l[128];
__device__ float g_s2w[256], g_t2w[256], g_s2l[256], g_t2l[256];

__device__ __forceinline__ unsigned f2tf(float v) {
    unsigned r;
    asm("cvt.rna.tf32.f32 %0, %1;" : "=r"(r) : "f"(v));
    return r;
}

__device__ __forceinline__ void mma_tf32(float* d, const unsigned* a, const unsigned* b) {
    asm volatile(
        "mma.sync.aligned.m16n8k8.row.col.f32.tf32.tf32.f32 "
        "{%0,%1,%2,%3}, {%4,%5,%6,%7}, {%8,%9}, {%0,%1,%2,%3};"
        : "+f"(d[0]), "+f"(d[1]), "+f"(d[2]), "+f"(d[3])
        : "r"(a[0]), "r"(a[1]), "r"(a[2]), "r"(a[3]), "r"(b[0]), "r"(b[1]));
}

// B (weights, K x N row-major input) -> tf32 fragment-major.
__device__ __forceinline__ void conv_frag(const float* __restrict__ W,
                                          float* __restrict__ Wf,
                                          int Kw, int Nw, int tid0, int nthreads)
{
    int total = Kw * Nw;
    for (int e = tid0; e < total; e += nthreads) {
        int kk = e / Nw, n = e - kk * Nw;
        int pos = (kk >> 4) * (Nw * 16)
                + (((kk >> 3) & 1) * (Nw >> 4) + (n >> 4)) * 128
                + (((n & 7) << 2) + (kk & 3)) * 4
                + (((n >> 3) & 1) << 1) + ((kk >> 2) & 1);
        Wf[pos] = __uint_as_float(f2tf(W[e]));
    }
}

// A fragment-major word index for element (m, k), M rows total.
__device__ __forceinline__ size_t posA(int m, int k, int M)
{
    return (size_t)(k >> 4) * (M * 16)
         + (size_t)(((k >> 3) & 1) * (M >> 4) + (m >> 4)) * 128
         + (((m & 7) << 2) + (k & 3)) * 4
         + ((m >> 3) & 1) + (((k >> 2) & 1) << 1);
}

// ---------------------------------------------------------------------------
// 1) Foveate: one sample per block (4096 blocks, 256 threads), 2x2-pooled
//    pyramid in SMEM, phi written tf32 fragment-major (scatter).
//    Aux: 0..31 where-layer1 (frag out), 32..79 W1 conv, 80..87 W2w, 88..95 W2l.
// ---------------------------------------------------------------------------
__global__ void __launch_bounds__(256) foveate_kernel(
    const float* __restrict__ x,
    const float* __restrict__ loc,
    const float* __restrict__ lW1,
    const float* __restrict__ lb1,
    const float* __restrict__ wW1,
    const float* __restrict__ wW2,
    const float* __restrict__ lW2)
{
    __shared__ float pooled[56 * 57];
    __shared__ float center[196];
    __shared__ float wrs[256], wrq[256];
    int tid = threadIdx.x;
    int b = blockIdx.x;

    float lx = loc[2 * b + 0];
    float ly = loc[2 * b + 1];
    int cx = (int)(0.5f * ((lx + 1.0f) * 128.0f));
    int cy = (int)(0.5f * ((ly + 1.0f) * 128.0f));
    int row0 = cy - 56;
    int col0 = cx - 56;
    const float* __restrict__ img = x + (size_t)b * HIMG * HIMG;

    for (int idx = tid; idx < 56 * 56; idx += 256) {
        int pr = idx / 56;
        int pc = idx - pr * 56;
        int r = row0 + 2 * pr;
        int c = col0 + 2 * pc;
        float sm = 0.0f;
        bool r0ok = (unsigned)r < 128u, r1ok = (unsigned)(r + 1) < 128u;
        bool c0ok = (unsigned)c < 128u, c1ok = (unsigned)(c + 1) < 128u;
        if (r0ok && c0ok) sm += img[r * HIMG + c];
        if (r0ok && c1ok) sm += img[r * HIMG + c + 1];
        if (r1ok && c0ok) sm += img[(r + 1) * HIMG + c];
        if (r1ok && c1ok) sm += img[(r + 1) * HIMG + c + 1];
        pooled[pr * 57 + pc] = sm * 0.25f;
    }
    if (tid < 196) {
        int i = tid / 14;
        int j = tid - i * 14;
        int r = row0 + 49 + i;
        int c = col0 + 49 + j;
        float v = 0.0f;
        if ((unsigned)r < 128u && (unsigned)c < 128u) v = img[r * HIMG + c];
        center[tid] = v;
    }
    __syncthreads();

    for (int o = tid; o < PHI_DIM; o += 256) {
        int p = o / 196;
        int rem = o - p * 196;
        int i = rem / 14;
        int j = rem - i * 14;
        float v;
        if (p == 0) {
            v = center[rem];
        } else if (p == 1) {
            v = pooled[(21 + i) * 57 + 21 + j];
        } else if (p == 2) {
            int base = (14 + 2 * i) * 57 + 14 + 2 * j;
            v = (pooled[base] + pooled[base + 1] +
                 pooled[base + 57] + pooled[base + 58]) * 0.25f;
        } else {
            int base = (4 * i) * 57 + 4 * j;
            float sm = 0.0f;
            #pragma unroll
            for (int di = 0; di < 4; di++)
                #pragma unroll
                for (int dj = 0; dj < 4; dj++)
                    sm += pooled[base + di * 57 + dj];
            v = sm * (1.0f / 16.0f);
        }
        g_phif[posA(b, o, BATCH)] = __uint_as_float(f2tf(v));
    }

    // ---- folded aux work ----
    if (b < 32) {
        int c = tid & 127;
        int half = tid >> 7;
        int r0 = b * 128 + half * 64;
        float w0 = lW1[c], w1 = lW1[128 + c], bb = lb1[c];
        float s = 0.0f, q = 0.0f;
        for (int r = r0; r < r0 + 64; r++) {
            float2 l = ((const float2*)loc)[r];
            float v = fmaf(l.x, w0, fmaf(l.y, w1, bb));
            g_h1lf[posA(r, c, BATCH)] = v;
            s += v;
            q += v * v;
        }
        wrs[tid] = s;
        wrq[tid] = q;
        __syncthreads();
        if (tid < 128) {
            g_p1l_s[b * 128 + tid] = wrs[tid] + wrs[tid + 128];
            g_p1l_q[b * 128 + tid] = wrq[tid] + wrq[tid + 128];
        }
    } else if (b < 80) {
        conv_frag(wW1, g_W1f, PHI_DIM, 128, (b - 32) * 256 + tid, 48 * 256);
    } else if (b < 88) {
        conv_frag(wW2, g_W2wf, 128, 256, (b - 80) * 256 + tid, 8 * 256);
    } else if (b < 96) {
        conv_frag(lW2, g_W2lf, 128, 256, (b - 88) * 256 + tid, 8 * 256);
    }
}

// ---------------------------------------------------------------------------
// 2) gemm1 (r8 config): BM=32 BN=64, WM=1 WN=2, grid (2,128)=256 blocks,
//    2-stage pipeline over K=784. Emits h1w frag + stats partials (128 rows).
// ---------------------------------------------------------------------------
__global__ void __launch_bounds__(256) gemm1_kernel(const float* __restrict__ b1)
{
    constexpr int N = 128, BM = 32, BN = 64;
    constexpr int STAGE_A = BM * 16;   // 512 floats
    constexpr int STAGE_B = BN * 16;   // 1024 floats
    constexpr int STAGE = STAGE_A + STAGE_B;   // 1536
    constexpr int CSS = BN + 4;        // 68
    constexpr int BUFSZ = 2 * STAGE;   // 3072 (> 32*68=2176)
    constexpr int STEPS = PHI_DIM / 16;  // 49

    __shared__ __align__(16) float buf[BUFSZ];
    __shared__ float rs[256], rq[256];

    const uint4*  Af = (const uint4*)g_phif;
    const float4* Bf = (const float4*)g_W1f;

    int tid = threadIdx.x;
    int lane = tid & 31;
    int wid = tid >> 5;
    int wn = wid & 3;    // 0..3
    int wm = wid >> 2;   // 0..1
    int nb = blockIdx.x; // 0..1
    int m0 = blockIdx.y * BM;
    int n0 = nb * BN;

    uint4  aReg;
    float4 bReg;

    auto ldA = [&](int step) {
        if (tid < 128) {
            int f = tid >> 5;           // 0..3
            int k8 = f >> 1, mt = f & 1;
            aReg = Af[(size_t)step * 16384 + (size_t)(k8 * 256 + (m0 >> 4) + mt) * 32 + lane];
        }
    };
    auto ldB = [&](int step) {
        int k8 = tid >> 7;
        int rem = tid & 127;
        bReg = Bf[(size_t)step * 512 + (size_t)(k8 * 256 + (n0 >> 4) * 32) + rem];
    };
    auto stA = [&](float* As) { if (tid < 128) ((uint4*)As)[tid] = aReg; };
    auto stB = [&](float* Bs) { ((float4*)Bs)[tid] = bReg; };

    float acc[2][4];
    #pragma unroll
    for (int j = 0; j < 2; j++)
        #pragma unroll
        for (int v = 0; v < 4; v++) acc[j][v] = 0.0f;

    auto compute = [&](const float* As, const float* Bs) {
        #pragma unroll
        for (int k8 = 0; k8 < 2; k8++) {
            unsigned a[4];
            *(uint4*)a = *(const uint4*)&((const unsigned*)As)[
                (k8 * 2 + wm) * 128 + lane * 4];
            uint4 bb = *(const uint4*)&((const unsigned*)Bs)[
                (k8 * 4 + wn) * 128 + lane * 4];
            unsigned bl[2] = {bb.x, bb.y};
            unsigned bh[2] = {bb.z, bb.w};
            mma_tf32(acc[0], a, bl);
            mma_tf32(acc[1], a, bh);
        }
    };

    ldA(0); ldB(0);
    stA(buf); stB(buf + STAGE_A);
    ldA(1); ldB(1);
    __syncthreads();

    for (int s = 0; s < STEPS; s++) {
        int cur = s & 1, nxt = cur ^ 1;
        float* curBuf = buf + cur * STAGE;
        if (s + 1 < STEPS) {
            float* nxtBuf = buf + nxt * STAGE;
            stA(nxtBuf);
            stB(nxtBuf + STAGE_A);
        }
        if (s + 2 < STEPS) { ldA(s + 2); ldB(s + 2); }
        compute(curBuf, curBuf + STAGE_A);
        __syncthreads();
    }

    // fragments -> Cs (stride 68)
    float* Cs = buf;
    {
        int row = wm * 16 + (lane >> 2);
        #pragma unroll
        for (int j = 0; j < 2; j++) {
            int cb = wn * 16 + j * 8 + 2 * (lane & 3);
            *(float2*)&Cs[row * CSS + cb]       = make_float2(acc[j][0], acc[j][1]);
            *(float2*)&Cs[(row + 8) * CSS + cb] = make_float2(acc[j][2], acc[j][3]);
        }
    }
    __syncthreads();

    // bias + stats, store back to Cs
    {
        int c = tid & 63;
        int h = tid >> 6;            // 0..3, 8 rows each
        float bb = b1[n0 + c];
        float s = 0.0f, q = 0.0f;
        #pragma unroll
        for (int i = 0; i < 8; i++) {
            int r = h * 8 + i;
            float v = Cs[r * CSS + c] + bb;
            Cs[r * CSS + c] = v;
            s += v;
            q += v * v;
        }
        rs[tid] = s;
        rq[tid] = q;
    }
    __syncthreads();
    if (tid < 64) {
        g_p1w_s[blockIdx.y * 128 + n0 + tid] = rs[tid] + rs[tid + 64] + rs[tid + 128] + rs[tid + 192];
        g_p1w_q[blockIdx.y * 128 + n0 + tid] = rq[tid] + rq[tid + 64] + rq[tid + 128] + rq[tid + 192];
    }
    __syncthreads();

    // emit raw-f32 fragment-major h1w: 32x64 tile -> 512 float4, 2/thread
    #pragma unroll
    for (int i2 = 0; i2 < 2; i2++) {
        int u = tid + i2 * 256;
        int l = u & 31;
        int f = u >> 5;           // 0..15
        int cl = f >> 2;          // local n16 chunk 0..3
        int rf = f & 3;
        int k8 = rf >> 1;
        int mt = rf & 1;
        int nl = cl * 16 + k8 * 8 + (l & 3);
        int rl = mt * 16 + (l >> 2);
        float4 o = make_float4(Cs[rl * CSS + nl],     Cs[(rl + 8) * CSS + nl],
                               Cs[rl * CSS + nl + 4], Cs[(rl + 8) * CSS + nl + 4]);
        ((float4*)g_h1wf)[(size_t)((n0 >> 4) + cl) * 16384 +
                          (size_t)(k8 * 256 + (m0 >> 4) + mt) * 32 + l] = o;
    }
}

// ---------------------------------------------------------------------------
// 3) gemm2: single-phase full-K-resident tf32 MMA. BM=64 BN=128 K=128.
//    512 threads = 16 warps (4m x 4n, warp tile 16x32). 96KB dyn SMEM,
//    grid (2,64,2) = 256 blocks, 2 blocks/SM, one wave.
// ---------------------------------------------------------------------------
#define G2_SMEM (24576 * 4)

__global__ void __launch_bounds__(512) gemm2_kernel(const float* __restrict__ wb2,
                                                    const float* __restrict__ lb2)
{
    extern __shared__ __align__(16) float dbuf[];   // [0,8192) A, [8192,24576) B
    __shared__ float rs[512], rq[512], sSc[128], sSh[128];

    int tid = threadIdx.x;
    int lane = tid & 31;
    int wid = tid >> 5;      // 0..15
    int wn = wid & 3;
    int wm = wid >> 2;       // 0..3
    int nb = blockIdx.x, mb = blockIdx.y, z = blockIdx.z;
    int m0 = mb * 64, n0 = nb * 128;

    const uint4*  Af = (const uint4*)(z ? g_h1lf : g_h1wf);
    const float4* Bf = (const float4*)(z ? g_W2lf : g_W2wf);
    const float*  bias = z ? lb2 : wb2;
    const float*  sA = z ? g_s1l : g_s1w;
    const float*  tA = z ? g_t1l : g_t1w;
    float* Cout = z ? g_h2l : g_h2w;
    float* ps = z ? g_p2l_s : g_p2w_s;
    float* pq = z ? g_p2l_q : g_p2w_q;

    if (tid < 128) { sSc[tid] = sA[tid]; sSh[tid] = tA[tid]; }

    // B panel copy: 4096 float4, 8 per thread
    float4* Bs = (float4*)(dbuf + 8192);
    #pragma unroll
    for (int i = 0; i < 8; i++) {
        int u = tid + i * 512;
        int s = u >> 9;
        int uu = u & 511;
        int k8 = uu >> 8;
        int rem = uu & 255;
        Bs[u] = Bf[(size_t)s * 1024 + k8 * 512 + (n0 >> 4) * 32 + rem];
    }
    __syncthreads();   // sSc/sSh visible

    // A panel: LDG.128 frag -> BN+ReLU+cvt -> STS.128.  2048 uint4, 4/thread.
    uint4* As = (uint4*)dbuf;
    #pragma unroll
    for (int i = 0; i < 4; i++) {
        int u = tid + i * 512;
        int s = u >> 8;
        int rem = u & 255;
        int f = rem >> 5;
        int k8 = f >> 2, mt = f & 3;
        int l = u & 31;
        uint4 a = Af[(size_t)s * 16384 + (size_t)(k8 * 256 + (m0 >> 4) + mt) * 32 + l];
        int kk = s * 16 + k8 * 8 + (l & 3);
        float sc0 = sSc[kk],     sh0 = sSh[kk];
        float sc4 = sSc[kk + 4], sh4 = sSh[kk + 4];
        uint4 o;
        o.x = f2tf(fmaxf(fmaf(__uint_as_float(a.x), sc0, sh0), 0.0f));
        o.y = f2tf(fmaxf(fmaf(__uint_as_float(a.y), sc0, sh0), 0.0f));
        o.z = f2tf(fmaxf(fmaf(__uint_as_float(a.z), sc4, sh4), 0.0f));
        o.w = f2tf(fmaxf(fmaf(__uint_as_float(a.w), sc4, sh4), 0.0f));
        As[u] = o;
    }
    __syncthreads();

    // compute: 16 syncless (s,k8) iterations, warp tile 16x32
    float acc[2][2][4];
    #pragma unroll
    for (int j = 0; j < 2; j++)
        #pragma unroll
        for (int h = 0; h < 2; h++)
            #pragma unroll
            for (int v = 0; v < 4; v++) acc[j][h][v] = 0.0f;

    const uint4* Bu = (const uint4*)Bs;
    #pragma unroll
    for (int s = 0; s < 8; s++) {
        #pragma unroll
        for (int k8 = 0; k8 < 2; k8++) {
            uint4 av = As[s * 256 + (k8 * 4 + wm) * 32 + lane];
            #pragma unroll
            for (int j = 0; j < 2; j++) {
                uint4 bb = Bu[s * 512 + (k8 * 8 + wn * 2 + j) * 32 + lane];
                unsigned bl[2] = {bb.x, bb.y};
                unsigned bh[2] = {bb.z, bb.w};
                mma_tf32(acc[j][0], (unsigned*)&av, bl);
                mma_tf32(acc[j][1], (unsigned*)&av, bh);
            }
        }
    }
    __syncthreads();   // before Cs overlay

    // fragments -> Cs (overlay dbuf; stride 132)
    float* Cs = dbuf;
    {
        int row = wm * 16 + (lane >> 2);
        #pragma unroll
        for (int j = 0; j < 2; j++) {
            #pragma unroll
            for (int h = 0; h < 2; h++) {
                int cb = wn * 32 + j * 16 + h * 8 + 2 * (lane & 3);
                *(float2*)&Cs[row * 132 + cb]       = make_float2(acc[j][h][0], acc[j][h][1]);
                *(float2*)&Cs[(row + 8) * 132 + cb] = make_float2(acc[j][h][2], acc[j][h][3]);
            }
        }
    }
    __syncthreads();

    // bias + row-major store + column stats
    {
        int c = tid & 127;
        int h = tid >> 7;    // 0..3, 16 rows each
        float bb = bias[n0 + c];
        float s = 0.0f, q = 0.0f;
        #pragma unroll
        for (int i = 0; i < 16; i++) {
            int r = h * 16 + i;
            float v = Cs[r * 132 + c] + bb;
            Cout[(size_t)(m0 + r) * 256 + n0 + c] = v;
            s += v;
            q += v * v;
        }
        rs[tid] = s;
        rq[tid] = q;
    }
    __syncthreads();
    if (tid < 128) {
        ps[mb * 256 + n0 + tid] = rs[tid] + rs[tid + 128] + rs[tid + 256] + rs[tid + 384];
        pq[mb * 256 + n0 + tid] = rq[tid] + rq[tid + 128] + rq[tid + 256] + rq[tid + 384];
    }
}

// ---------------------------------------------------------------------------
// 4) Parallel finalize: one block per column.
// ---------------------------------------------------------------------------
__device__ __forceinline__ void reduce_finalize(float s, float q, int c,
                                                const float* __restrict__ gam,
                                                const float* __restrict__ bet,
                                                float* __restrict__ sc_out,
                                                float* __restrict__ sh_out)
{
    __shared__ float rs[128], rq[128];
    rs[threadIdx.x] = s;
    rq[threadIdx.x] = q;
    __syncthreads();
    #pragma unroll
    for (int off = 64; off >= 32; off >>= 1) {
        if (threadIdx.x < off) {
            rs[threadIdx.x] += rs[threadIdx.x + off];
            rq[threadIdx.x] += rq[threadIdx.x + off];
        }
        __syncthreads();
    }
    if (threadIdx.x < 32) {
        float ss = rs[threadIdx.x];
        float qq = rq[threadIdx.x];
        #pragma unroll
        for (int off = 16; off > 0; off >>= 1) {
            ss += __shfl_down_sync(0xffffffffu, ss, off);
            qq += __shfl_down_sync(0xffffffffu, qq, off);
        }
        if (threadIdx.x == 0) {
            float m = ss * (1.0f / BATCH);
            float var = qq * (1.0f / BATCH) - m * m;
            float r = rsqrtf(var + 1e-5f);
            float sc = r * gam[c];
            sc_out[c] = sc;
            sh_out[c] = bet[c] - m * sc;
        }
    }
}

__global__ void finalize1_kernel(const float* __restrict__ g1w, const float* __restrict__ be1w,
                                 const float* __restrict__ g1l, const float* __restrict__ be1l)
{
    int t = threadIdx.x;
    if (blockIdx.x < 128) {
        int c = blockIdx.x;
        reduce_finalize(g_p1w_s[t * 128 + c], g_p1w_q[t * 128 + c],
                        c, g1w, be1w, g_s1w, g_t1w);
    } else {
        int c = blockIdx.x - 128;
        float s = (t < 32) ? g_p1l_s[t * 128 + c] : 0.0f;
        float q = (t < 32) ? g_p1l_q[t * 128 + c] : 0.0f;
        reduce_finalize(s, q, c, g1l, be1l, g_s1l, g_t1l);
    }
}

__global__ void finalize2_kernel(const float* __restrict__ g2w, const float* __restrict__ be2w,
                                 const float* __restrict__ g2l, const float* __restrict__ be2l)
{
    int t = threadIdx.x;
    if (blockIdx.x < 256) {
        int c = blockIdx.x;
        float s = (t < 64) ? g_p2w_s[t * 256 + c] : 0.0f;
        float q = (t < 64) ? g_p2w_q[t * 256 + c] : 0.0f;
        reduce_finalize(s, q, c, g2w, be2w, g_s2w, g_t2w);
    } else {
        int c = blockIdx.x - 256;
        float s = (t < 64) ? g_p2l_s[t * 256 + c] : 0.0f;
        float q = (t < 64) ? g_p2l_q[t * 256 + c] : 0.0f;
        reduce_finalize(s, q, c, g2l, be2l, g_s2l, g_t2l);
    }
}

// ---------------------------------------------------------------------------
// 5) Final: out = relu( BN(h2w) + BN(h2l) ), float4 vectorized.
// ---------------------------------------------------------------------------
__global__ void final_kernel(float* __restrict__ out)
{
    int idx = blockIdx.x * 256 + threadIdx.x;   // float4 index
    int c0 = (idx & 63) << 2;
    float4 w = ((const float4*)g_h2w)[idx];
    float4 l = ((const float4*)g_h2l)[idx];
    float4 o;
    o.x = fmaf(w.x, g_s2w[c0+0], g_t2w[c0+0]) + fmaf(l.x, g_s2l[c0+0], g_t2l[c0+0]);
    o.y = fmaf(w.y, g_s2w[c0+1], g_t2w[c0+1]) + fmaf(l.y, g_s2l[c0+1], g_t2l[c0+1]);
    o.z = fmaf(w.z, g_s2w[c0+2], g_t2w[c0+2]) + fmaf(l.z, g_s2l[c0+2], g_t2l[c0+2]);
    o.w = fmaf(w.w, g_s2w[c0+3], g_t2w[c0+3]) + fmaf(l.w, g_s2l[c0+3], g_t2l[c0+3]);
    o.x = o.x > 0.0f ? o.x : 0.0f;
    o.y = o.y > 0.0f ? o.y : 0.0f;
    o.z = o.z > 0.0f ? o.z : 0.0f;
    o.w = o.w > 0.0f ? o.w : 0.0f;
    ((float4*)out)[idx] = o;
}

// ---------------------------------------------------------------------------
extern "C" void kernel_launch(void* const* d_in, const int* in_sizes, int n_in,
                              void* d_out, int out_size)
{
    const float* x    = (const float*)d_in[0];
    const float* loc  = (const float*)d_in[1];
    const float* wW1  = (const float*)d_in[2];
    const float* wb1  = (const float*)d_in[3];
    const float* wg1  = (const float*)d_in[4];
    const float* wbe1 = (const float*)d_in[5];
    const float* wW2  = (const float*)d_in[6];
    const float* wb2  = (const float*)d_in[7];
    const float* wg2  = (const float*)d_in[8];
    const float* wbe2 = (const float*)d_in[9];
    const float* lW1  = (const float*)d_in[10];
    const float* lb1  = (const float*)d_in[11];
    const float* lg1  = (const float*)d_in[12];
    const float* lbe1 = (const float*)d_in[13];
    const float* lW2  = (const float*)d_in[14];
    const float* lb2  = (const float*)d_in[15];
    const float* lg2  = (const float*)d_in[16];
    const float* lbe2 = (const float*)d_in[17];
    float* out = (float*)d_out;

    static int smem_set = 0;
    if (!smem_set) {
        cudaFuncSetAttribute(gemm2_kernel,
                             cudaFuncAttributeMaxDynamicSharedMemorySize, G2_SMEM);
        smem_set = 1;
    }

    // 1) foveate (one sample/block) + where1 + weight conversions
    foveate_kernel<<<BATCH, 256>>>(x, loc, lW1, lb1, wW1, wW2, lW2);

    // 2) what layer1 -> h1w frag (+ stats partials), 256 blocks
    {
        dim3 grid(2, BATCH / 32);
        gemm1_kernel<<<grid, 256>>>(wb1);
    }

    // 3) finalize layer-1 BN params
    finalize1_kernel<<<256, 128>>>(wg1, wbe1, lg1, lbe1);

    // 4) both layer-2 GEMMs, single-phase full-K, 16 warps/block, 256 blocks
    {
        dim3 grid(2, BATCH / 64, 2);
        gemm2_kernel<<<grid, 512, G2_SMEM>>>(wb2, lb2);
    }

    // 5) finalize layer-2 BN params
    finalize2_kernel<<<512, 128>>>(wg2, wbe2, lg2, lbe2);

    // 6) final add + relu (float4)
    final_kernel<<<BATCH * 64 / 256, 256>>>(out);
}